// round 2
// baseline (speedup 1.0000x reference)
#include <cuda_runtime.h>
#include <cuda_fp16.h>
#include <cstdint>

// Problem constants (fixed by the dataset)
constexpr int N = 8192;
constexpr int F = 256;

// ---------------- scratch (no allocations allowed) ----------------
__device__ __align__(16) float  g_H [(size_t)N * F];  // H = x@W + bias (fp32)
__device__ __align__(16) __half g_Hh[(size_t)N * F];  // H in fp16 (gather copy)
__device__ float g_edst[N];                           // exp(H @ phi[F:2F])

// packed fp32x2 FMA: d = a*b + d  (FFMA2, 2x fp32 FMA throughput on sm_103a)
__device__ __forceinline__ void fma2(float2& d, const float2& a, const float2& b) {
    asm("fma.rn.f32x2 %0, %1, %2, %0;"
        : "+l"(reinterpret_cast<unsigned long long&>(d))
        : "l"(reinterpret_cast<const unsigned long long&>(a)),
          "l"(reinterpret_cast<const unsigned long long&>(b)));
}

// ---------------- Kernel 1: H = x @ W + bias  (128x128x16, FFMA2) ----------
__global__ void __launch_bounds__(256, 2)
gemm_bias_kernel(const float* __restrict__ A,   // x [N, F]
                 const float* __restrict__ B,   // W [F, F]
                 const float* __restrict__ bias,
                 float* __restrict__ C,         // H fp32 [N, F]
                 __half* __restrict__ Ch)       // H fp16 [N, F]
{
    constexpr int BM = 128, BN = 128, BK = 16;
    __shared__ float2 As2[BK][BM];   // duplicated {v, v} for FFMA2 broadcast
    __shared__ float  Bs[BK][BN];

    const int tid = threadIdx.x;
    const int tx = tid & 15;        // 0..15 -> owns cols tx*8 .. tx*8+7
    const int ty = tid >> 4;        // 0..15 -> owns rows ty*8 .. ty*8+7
    const int row0 = blockIdx.y * BM;
    const int col0 = blockIdx.x * BN;

    float2 acc2[8][4];              // [m][n-pair]
#pragma unroll
    for (int m = 0; m < 8; ++m)
#pragma unroll
        for (int n = 0; n < 4; ++n) acc2[m][n] = make_float2(0.f, 0.f);

    for (int k0 = 0; k0 < F; k0 += BK) {
        // A tile (BM x BK) -> As2 transposed, value duplicated
#pragma unroll
        for (int l = 0; l < 2; ++l) {
            int idx = tid + l * 256;          // 0..511 float4s
            int r  = idx >> 2;                // 0..127
            int kk = (idx & 3) << 2;          // 0,4,8,12
            float4 v = *reinterpret_cast<const float4*>(
                A + (size_t)(row0 + r) * F + k0 + kk);
            As2[kk + 0][r] = make_float2(v.x, v.x);
            As2[kk + 1][r] = make_float2(v.y, v.y);
            As2[kk + 2][r] = make_float2(v.z, v.z);
            As2[kk + 3][r] = make_float2(v.w, v.w);
        }
        // B tile (BK x BN)
#pragma unroll
        for (int l = 0; l < 2; ++l) {
            int idx = tid + l * 256;
            int kk = idx >> 5;                // 0..15
            int c  = (idx & 31) << 2;         // 0..124
            *reinterpret_cast<float4*>(&Bs[kk][c]) =
                *reinterpret_cast<const float4*>(B + (size_t)(k0 + kk) * F + col0 + c);
        }
        __syncthreads();

#pragma unroll
        for (int kk = 0; kk < BK; ++kk) {
            float2 a2[8], b2[4];
#pragma unroll
            for (int m = 0; m < 8; ++m) a2[m] = As2[kk][ty * 8 + m];
#pragma unroll
            for (int n = 0; n < 4; ++n)
                b2[n] = *reinterpret_cast<const float2*>(&Bs[kk][tx * 8 + n * 2]);
#pragma unroll
            for (int m = 0; m < 8; ++m)
#pragma unroll
                for (int n = 0; n < 4; ++n) fma2(acc2[m][n], a2[m], b2[n]);
        }
        __syncthreads();
    }

    // epilogue: bias, store fp32 + fp16 copies
#pragma unroll
    for (int m = 0; m < 8; ++m) {
        int row = row0 + ty * 8 + m;
#pragma unroll
        for (int n = 0; n < 4; ++n) {
            int col = col0 + tx * 8 + n * 2;
            float vx = acc2[m][n].x + bias[col + 0];
            float vy = acc2[m][n].y + bias[col + 1];
            *reinterpret_cast<float2*>(C + (size_t)row * F + col) = make_float2(vx, vy);
            *reinterpret_cast<__half2*>(Ch + (size_t)row * F + col) = __floats2half2_rn(vx, vy);
        }
    }
}

// ---------------- Kernel 2: edst[i] = exp(dot(H[i], phi[F:2F])) -------------
// Row-softmax is shift-invariant; |s| < ~30 so exp(s) is safe in fp32 and the
// global-max subtraction is unnecessary.
__global__ void __launch_bounds__(256)
sdst_exp_kernel(const float* __restrict__ H, const float* __restrict__ phi,
                float* __restrict__ edst)
{
    __shared__ float ph[F];
    for (int i = threadIdx.x; i < F; i += blockDim.x) ph[i] = phi[F + i];
    __syncthreads();

    const int lane = threadIdx.x & 31;
    const int warp = threadIdx.x >> 5;
    const int row = blockIdx.x * 8 + warp;

    const float4* h = reinterpret_cast<const float4*>(H + (size_t)row * F) + lane * 2;
    float4 a = h[0], b = h[1];
    const float* p = ph + lane * 8;
    float s = a.x * p[0] + a.y * p[1] + a.z * p[2] + a.w * p[3]
            + b.x * p[4] + b.y * p[5] + b.z * p[6] + b.w * p[7];
#pragma unroll
    for (int off = 16; off > 0; off >>= 1)
        s += __shfl_xor_sync(0xFFFFFFFFu, s, off);
    if (lane == 0) edst[row] = expf(s);
}

// ---------------- Kernel 3: fused masked-softmax aggregation + leaky relu ---
// warp per row: scan adj[row, :] (float4), enumerate nonzeros via ballot,
// accumulate e_dst[j] * Hh[j, :] (fp16 loads, fp32 accum); normalize; lrelu.
__global__ void __launch_bounds__(256)
gat_aggregate_kernel(const float* __restrict__ adj,
                     const float* __restrict__ H,     // fp32 (self term)
                     const __half* __restrict__ Hh,   // fp16 (gather)
                     const float* __restrict__ edst,
                     float* __restrict__ out)
{
    const int lane = threadIdx.x & 31;
    const int warp = threadIdx.x >> 5;
    const int row = blockIdx.x * 8 + warp;

    const float4* arow = reinterpret_cast<const float4*>(adj + (size_t)row * N);

    // self-loop (diag always unmasked), fp32, counted exactly once
    float e0 = __ldg(&edst[row]);
    float Z = e0;
    const float4* hself = reinterpret_cast<const float4*>(H + (size_t)row * F) + lane * 2;
    float4 p = hself[0], q = hself[1];
    float acc[8];
    acc[0] = e0 * p.x; acc[1] = e0 * p.y; acc[2] = e0 * p.z; acc[3] = e0 * p.w;
    acc[4] = e0 * q.x; acc[5] = e0 * q.y; acc[6] = e0 * q.z; acc[7] = e0 * q.w;

#pragma unroll 2
    for (int it = 0; it < N / 128; ++it) {      // 64 iterations
        float4 v = arow[it * 32 + lane];
        int jb = it * 128 + lane * 4;           // column index of v.x
        unsigned b0 = __ballot_sync(0xFFFFFFFFu, v.x != 0.f && (jb + 0) != row);
        unsigned b1 = __ballot_sync(0xFFFFFFFFu, v.y != 0.f && (jb + 1) != row);
        unsigned b2 = __ballot_sync(0xFFFFFFFFu, v.z != 0.f && (jb + 2) != row);
        unsigned b3 = __ballot_sync(0xFFFFFFFFu, v.w != 0.f && (jb + 3) != row);
        int base = it * 128;

        unsigned masks[4] = {b0, b1, b2, b3};
#pragma unroll
        for (int c = 0; c < 4; ++c) {
            unsigned m = masks[c];
            while (m) {
                int l = __ffs(m) - 1;
                m &= m - 1;
                int j = base + l * 4 + c;
                float e = __ldg(&edst[j]);
                Z += e;
                // one 16B load = 8 halves = this lane's 8 columns
                uint4 hraw = __ldg(reinterpret_cast<const uint4*>(
                    Hh + (size_t)j * F) + lane);
                float2 f0 = __half22float2(*reinterpret_cast<__half2*>(&hraw.x));
                float2 f1 = __half22float2(*reinterpret_cast<__half2*>(&hraw.y));
                float2 f2 = __half22float2(*reinterpret_cast<__half2*>(&hraw.z));
                float2 f3 = __half22float2(*reinterpret_cast<__half2*>(&hraw.w));
                acc[0] += e * f0.x; acc[1] += e * f0.y;
                acc[2] += e * f1.x; acc[3] += e * f1.y;
                acc[4] += e * f2.x; acc[5] += e * f2.y;
                acc[6] += e * f3.x; acc[7] += e * f3.y;
            }
        }
    }

    const float inv = 1.0f / Z;
    float4 o0, o1;
    o0.x = acc[0] * inv; o0.y = acc[1] * inv; o0.z = acc[2] * inv; o0.w = acc[3] * inv;
    o1.x = acc[4] * inv; o1.y = acc[5] * inv; o1.z = acc[6] * inv; o1.w = acc[7] * inv;
    o0.x = o0.x > 0.f ? o0.x : 0.01f * o0.x;
    o0.y = o0.y > 0.f ? o0.y : 0.01f * o0.y;
    o0.z = o0.z > 0.f ? o0.z : 0.01f * o0.z;
    o0.w = o0.w > 0.f ? o0.w : 0.01f * o0.w;
    o1.x = o1.x > 0.f ? o1.x : 0.01f * o1.x;
    o1.y = o1.y > 0.f ? o1.y : 0.01f * o1.y;
    o1.z = o1.z > 0.f ? o1.z : 0.01f * o1.z;
    o1.w = o1.w > 0.f ? o1.w : 0.01f * o1.w;

    float4* orow = reinterpret_cast<float4*>(out + (size_t)row * F) + lane * 2;
    orow[0] = o0;
    orow[1] = o1;
}

// ---------------- launch ----------------
extern "C" void kernel_launch(void* const* d_in, const int* in_sizes, int n_in,
                              void* d_out, int out_size)
{
    const float* adj    = (const float*)d_in[0];   // [N, N]
    const float* x      = (const float*)d_in[1];   // [N, F]
    const float* weight = (const float*)d_in[2];   // [F, F]
    const float* bias   = (const float*)d_in[3];   // [F]
    const float* phi    = (const float*)d_in[4];   // [2F, 1]
    float* out = (float*)d_out;                    // [N, F]

    float*  H    = nullptr;
    __half* Hh   = nullptr;
    float*  edst = nullptr;
    cudaGetSymbolAddress((void**)&H,    g_H);
    cudaGetSymbolAddress((void**)&Hh,   g_Hh);
    cudaGetSymbolAddress((void**)&edst, g_edst);

    dim3 ggrid(F / 128, N / 128);
    gemm_bias_kernel<<<ggrid, 256>>>(x, weight, bias, H, Hh);
    sdst_exp_kernel<<<N / 8, 256>>>(H, phi, edst);
    gat_aggregate_kernel<<<N / 8, 256>>>(adj, H, Hh, edst, out);
}